// round 3
// baseline (speedup 1.0000x reference)
#include <cuda_runtime.h>
#include <cuda_bf16.h>
#include <cstddef>

// RandCropResize, table-driven + shared staging.
//
// Phase A (setup kernel, 64x512 threads): precompute per-batch tap tables.
//   xtab[b][w] = {l0, l1, wx}   (smem-relative horizontal taps; depend only on b,w)
//   ytab[b][h] = {ay0, ay1, wy} (absolute source rows; depend only on b,h)
// This removes ALL per-pixel coordinate math from the hot kernel.
//
// Phase B (main kernel, block=(h,b), 512 thr): stage the two source rows with
// coalesced float4 loads, fusing the y-lerp into shared memory (once per
// source column instead of once per output pixel). Main loop per pixel:
// 1 LDG.128 (xtab) + 6 LDS + 6 FFMA + 3 coalesced STG.

#define IMG_H 512
#define IMG_W 512
#define IMG_C 3
#define SPITCH 520            // smem row pitch (floats), float4-aligned

__device__ int4 g_xtab[64 * IMG_W];
__device__ int4 g_ytab[64 * IMG_H];

__global__ void __launch_bounds__(512)
setup_tables_kernel(const int* __restrict__ y1v, const int* __restrict__ y2v,
                    const int* __restrict__ x1v, const int* __restrict__ x2v)
{
    const int b = blockIdx.x;
    const int t = threadIdx.x;

    const int Y1 = y1v[b], Y2 = y2v[b];
    const int X1 = x1v[b], X2 = x2v[b];

    // ---- y table entry for h = t ----
    {
        const int   ncy = Y2 - Y1;
        const float ny  = (float)ncy;
        float sy = ((float)t + 0.5f) * ny * (1.0f / (float)IMG_H) - 0.5f;
        sy = fminf(fmaxf(sy, 0.0f), ny - 1.0f);
        const int   iy0 = (int)floorf(sy);
        const int   iy1 = min(iy0 + 1, ncy - 1);
        const float wy  = sy - (float)iy0;
        int4 e;
        e.x = Y1 + iy0;
        e.y = Y1 + iy1;
        e.z = __float_as_int(wy);
        e.w = 0;
        g_ytab[(b << 9) + t] = e;
    }

    // ---- x table entry for w = t (smem-relative: minus xlo) ----
    {
        const int   xlo = X1 & ~3;
        const int   ncx = X2 - X1;
        const float nx  = (float)ncx;
        float sx = ((float)t + 0.5f) * nx * (1.0f / (float)IMG_W) - 0.5f;
        sx = fminf(fmaxf(sx, 0.0f), nx - 1.0f);
        const int   ix0 = (int)floorf(sx);
        const int   ix1 = min(ix0 + 1, ncx - 1);
        const float wx  = sx - (float)ix0;
        int4 e;
        e.x = (X1 + ix0) - xlo;
        e.y = (X1 + ix1) - xlo;
        e.z = __float_as_int(wx);
        e.w = 0;
        g_xtab[(b << 9) + t] = e;
    }
}

__global__ void __launch_bounds__(512)
rand_crop_resize_kernel(const float* __restrict__ img,
                        const int* __restrict__ x1v,
                        const int* __restrict__ x2v,
                        float* __restrict__ out)
{
    __shared__ float srow[IMG_C * SPITCH];

    const int h   = blockIdx.x;
    const int b   = blockIdx.y;
    const int tid = threadIdx.x;

    // block-uniform x staging span
    const int X1    = x1v[b];
    const int X2    = x2v[b];
    const int xlo   = X1 & ~3;
    const int span4 = (((X2 + 3) & ~3) - xlo) >> 2;   // <= 128 float4s per row

    // block-uniform y taps (broadcast load)
    const int4  ye  = g_ytab[(b << 9) + h];
    const int   ay0 = ye.x;
    const int   ay1 = ye.y;
    const float wy  = __int_as_float(ye.z);

    const size_t img_stride = (size_t)IMG_H * IMG_W;
    const float* base = img + (size_t)b * IMG_C * img_stride;

    // ---- staging: one float4 per active thread, no div, no loop ----
    const int ns = 3 * span4;                 // <= 384 <= blockDim
    if (tid < ns) {
        const int c  = (tid >= span4) + (tid >= 2 * span4);
        const int xq = tid - c * span4;
        const float* p = base + (size_t)c * img_stride + xlo + (xq << 2);
        const float4 v0 = *(const float4*)(p + (size_t)ay0 * IMG_W);
        const float4 v1 = *(const float4*)(p + (size_t)ay1 * IMG_W);
        float4 f;
        f.x = v0.x + (v1.x - v0.x) * wy;
        f.y = v0.y + (v1.y - v0.y) * wy;
        f.z = v0.z + (v1.z - v0.z) * wy;
        f.w = v0.w + (v1.w - v0.w) * wy;
        *(float4*)(&srow[c * SPITCH + (xq << 2)]) = f;
    }
    __syncthreads();

    // ---- main: table lookup + horizontal lerp ----
    const int4  xe = g_xtab[(b << 9) + tid];
    const int   l0 = xe.x;
    const int   l1 = xe.y;
    const float wx = __int_as_float(xe.z);

    float* obase = out + (size_t)b * IMG_C * img_stride
                       + (size_t)h * IMG_W + tid;
#pragma unroll
    for (int c = 0; c < IMG_C; c++) {
        const float f0 = srow[c * SPITCH + l0];
        const float f1 = srow[c * SPITCH + l1];
        obase[(size_t)c * img_stride] = f0 + (f1 - f0) * wx;
    }
}

extern "C" void kernel_launch(void* const* d_in, const int* in_sizes, int n_in,
                              void* d_out, int out_size)
{
    const float* img = (const float*)d_in[0];
    const int*   y1  = (const int*)d_in[1];
    const int*   y2  = (const int*)d_in[2];
    const int*   x1  = (const int*)d_in[3];
    const int*   x2  = (const int*)d_in[4];
    float*       out = (float*)d_out;

    setup_tables_kernel<<<64, 512>>>(y1, y2, x1, x2);

    dim3 grid(IMG_H, 64);   // (h, b)
    dim3 block(IMG_W);
    rand_crop_resize_kernel<<<grid, block>>>(img, x1, x2, out);
}

// round 5
// speedup vs baseline: 1.4772x; 1.4772x over previous
#include <cuda_runtime.h>
#include <cuda_bf16.h>
#include <cstddef>

// RandCropResize: table-driven direct gather, no shared memory, no barrier.
//
// Setup kernel precomputes packed tap tables per batch:
//   xtab[b][pair] = int4{ ax0a|ax1a<<16, bits(wxa), ax0b|ax1b<<16, bits(wxb) }
//                   (x taps for the two adjacent pixels 2*pair, 2*pair+1)
//   ytab[b][h]    = int2{ ay0 | ay1<<16 , bits(wy) }
//
// Main kernel: 256 threads per output row; each thread produces 2 adjacent
// pixels x 3 channels. One aligned LDG.128 fetches both pixels' x-taps,
// y-taps are a block-uniform L1-hit load, then 24 independent LDG.32 gathers
// (high MLP), 18 FFMA, 3 aligned STG.64. ~11 instructions per output value.

#define IMG_H 512
#define IMG_W 512
#define IMG_C 3

__device__ int4 g_xtab[64 * (IMG_W / 2)];   // one int4 per pixel pair, 16B aligned
__device__ int2 g_ytab[64 * IMG_H];

__device__ __forceinline__ void x_taps(int w, int X1, int X2,
                                       int& packed, float& wx)
{
    const int   ncx = X2 - X1;
    const float nx  = (float)ncx;
    float sx = ((float)w + 0.5f) * nx * (1.0f / (float)IMG_W) - 0.5f;
    sx = fminf(fmaxf(sx, 0.0f), nx - 1.0f);
    const int ix0 = (int)floorf(sx);
    const int ix1 = min(ix0 + 1, ncx - 1);
    wx = sx - (float)ix0;
    packed = (X1 + ix0) | ((X1 + ix1) << 16);
}

__global__ void __launch_bounds__(512)
setup_tables_kernel(const int* __restrict__ y1v, const int* __restrict__ y2v,
                    const int* __restrict__ x1v, const int* __restrict__ x2v)
{
    const int b = blockIdx.x;
    const int t = threadIdx.x;

    const int Y1 = y1v[b], Y2 = y2v[b];
    const int X1 = x1v[b], X2 = x2v[b];

    // y taps for h = t (all 512 threads)
    {
        const int   ncy = Y2 - Y1;
        const float ny  = (float)ncy;
        float sy = ((float)t + 0.5f) * ny * (1.0f / (float)IMG_H) - 0.5f;
        sy = fminf(fmaxf(sy, 0.0f), ny - 1.0f);
        const int   iy0 = (int)floorf(sy);
        const int   iy1 = min(iy0 + 1, ncy - 1);
        const float wy  = sy - (float)iy0;
        int2 e;
        e.x = (Y1 + iy0) | ((Y1 + iy1) << 16);
        e.y = __float_as_int(wy);
        g_ytab[(b << 9) + t] = e;
    }

    // x taps: threads 0..255 each build one pixel-pair entry
    if (t < (IMG_W / 2)) {
        int   pa, pb;
        float wxa, wxb;
        x_taps(2 * t,     X1, X2, pa, wxa);
        x_taps(2 * t + 1, X1, X2, pb, wxb);
        int4 e;
        e.x = pa;
        e.y = __float_as_int(wxa);
        e.z = pb;
        e.w = __float_as_int(wxb);
        g_xtab[b * (IMG_W / 2) + t] = e;
    }
}

__global__ void __launch_bounds__(256)
rand_crop_resize_kernel(const float* __restrict__ img,
                        float* __restrict__ out)
{
    const int h   = blockIdx.x;
    const int b   = blockIdx.y;
    const int tid = threadIdx.x;
    const int w0  = tid << 1;                 // first of 2 adjacent pixels

    // block-uniform y taps (L1 broadcast)
    const int2  ye  = __ldg(&g_ytab[(b << 9) + h]);
    const int   ay0 = ye.x & 0xFFFF;
    const int   ay1 = ye.x >> 16;
    const float wy  = __int_as_float(ye.y);

    // two pixels' x taps in one aligned 128-bit load
    const int4  xe   = __ldg(&g_xtab[b * (IMG_W / 2) + tid]);
    const int   ax0a = xe.x & 0xFFFF;
    const int   ax1a = xe.x >> 16;
    const float wxa  = __int_as_float(xe.y);
    const int   ax0b = xe.z & 0xFFFF;
    const int   ax1b = xe.z >> 16;
    const float wxb  = __int_as_float(xe.w);

    const size_t img_stride = (size_t)IMG_H * IMG_W;
    const float* base = img + (size_t)b * IMG_C * img_stride;
    const float* r0   = base + (size_t)ay0 * IMG_W;
    const float* r1   = base + (size_t)ay1 * IMG_W;

    // issue all 24 gathers up front for maximum MLP
    float v[24];
#pragma unroll
    for (int c = 0; c < IMG_C; c++) {
        const float* p0 = r0 + (size_t)c * img_stride;
        const float* p1 = r1 + (size_t)c * img_stride;
        v[c * 8 + 0] = __ldg(p0 + ax0a);
        v[c * 8 + 1] = __ldg(p0 + ax1a);
        v[c * 8 + 2] = __ldg(p1 + ax0a);
        v[c * 8 + 3] = __ldg(p1 + ax1a);
        v[c * 8 + 4] = __ldg(p0 + ax0b);
        v[c * 8 + 5] = __ldg(p0 + ax1b);
        v[c * 8 + 6] = __ldg(p1 + ax0b);
        v[c * 8 + 7] = __ldg(p1 + ax1b);
    }

    float* obase = out + (size_t)b * IMG_C * img_stride
                       + (size_t)h * IMG_W + w0;
#pragma unroll
    for (int c = 0; c < IMG_C; c++) {
        // y-lerp first (matches reference order), then x-lerp
        const float a0 = v[c * 8 + 0] + (v[c * 8 + 2] - v[c * 8 + 0]) * wy;
        const float a1 = v[c * 8 + 1] + (v[c * 8 + 3] - v[c * 8 + 1]) * wy;
        const float b0 = v[c * 8 + 4] + (v[c * 8 + 6] - v[c * 8 + 4]) * wy;
        const float b1 = v[c * 8 + 5] + (v[c * 8 + 7] - v[c * 8 + 5]) * wy;
        float2 o;
        o.x = a0 + (a1 - a0) * wxa;
        o.y = b0 + (b1 - b0) * wxb;
        *(float2*)(obase + (size_t)c * img_stride) = o;
    }
}

extern "C" void kernel_launch(void* const* d_in, const int* in_sizes, int n_in,
                              void* d_out, int out_size)
{
    const float* img = (const float*)d_in[0];
    const int*   y1  = (const int*)d_in[1];
    const int*   y2  = (const int*)d_in[2];
    const int*   x1  = (const int*)d_in[3];
    const int*   x2  = (const int*)d_in[4];
    float*       out = (float*)d_out;

    setup_tables_kernel<<<64, 512>>>(y1, y2, x1, x2);

    dim3 grid(IMG_H, 64);       // (h, b)
    dim3 block(256);            // 2 pixels per thread
    rand_crop_resize_kernel<<<grid, block>>>(img, out);
}

// round 6
// speedup vs baseline: 1.4959x; 1.0126x over previous
#include <cuda_runtime.h>
#include <cuda_bf16.h>
#include <cstddef>

// RandCropResize: tap tables + multi-row shared staging.
//
// Block = (4 output rows, batch b), 512 threads. Staging phase: for each of
// the 4 rows, coalesced float4 loads of the two source rows with the y-lerp
// fused into shared memory. ONE __syncthreads per block (amortized over
// 4*512*3 = 6144 outputs). Main phase: per output value, 2 conflict-free LDS
// + 2 FFMA + 1 coalesced STG. x-tap table lookup done once per thread and
// reused for all 4 rows.

#define IMG_H 512
#define IMG_W 512
#define IMG_C 3
#define HGROUP 4              // output rows per block
#define SPITCH 520            // smem row pitch (floats), float4-aligned

__device__ int2 g_xtab[64 * IMG_W];   // {l0|l1<<16 relative? no: l0, l1 packed} see below
__device__ int2 g_ytab[64 * IMG_H];

__global__ void __launch_bounds__(512)
setup_tables_kernel(const int* __restrict__ y1v, const int* __restrict__ y2v,
                    const int* __restrict__ x1v, const int* __restrict__ x2v)
{
    const int b = blockIdx.x;
    const int t = threadIdx.x;

    const int Y1 = y1v[b], Y2 = y2v[b];
    const int X1 = x1v[b], X2 = x2v[b];

    // y taps for h = t (absolute source rows)
    {
        const int   ncy = Y2 - Y1;
        const float ny  = (float)ncy;
        float sy = ((float)t + 0.5f) * ny * (1.0f / (float)IMG_H) - 0.5f;
        sy = fminf(fmaxf(sy, 0.0f), ny - 1.0f);
        const int   iy0 = (int)floorf(sy);
        const int   iy1 = min(iy0 + 1, ncy - 1);
        const float wy  = sy - (float)iy0;
        int2 e;
        e.x = (Y1 + iy0) | ((Y1 + iy1) << 16);
        e.y = __float_as_int(wy);
        g_ytab[(b << 9) + t] = e;
    }

    // x taps for w = t (smem-relative: minus xlo)
    {
        const int   xlo = X1 & ~3;
        const int   ncx = X2 - X1;
        const float nx  = (float)ncx;
        float sx = ((float)t + 0.5f) * nx * (1.0f / (float)IMG_W) - 0.5f;
        sx = fminf(fmaxf(sx, 0.0f), nx - 1.0f);
        const int   ix0 = (int)floorf(sx);
        const int   ix1 = min(ix0 + 1, ncx - 1);
        const float wx  = sx - (float)ix0;
        int2 e;
        e.x = ((X1 + ix0) - xlo) | (((X1 + ix1) - xlo) << 16);
        e.y = __float_as_int(wx);
        g_xtab[(b << 9) + t] = e;
    }
}

__global__ void __launch_bounds__(512)
rand_crop_resize_kernel(const float* __restrict__ img,
                        const int* __restrict__ x1v,
                        const int* __restrict__ x2v,
                        float* __restrict__ out)
{
    __shared__ float srow[HGROUP * IMG_C * SPITCH];   // 24.4 KB

    const int hbase = blockIdx.x * HGROUP;
    const int b     = blockIdx.y;
    const int tid   = threadIdx.x;

    // block-uniform x staging span
    const int X1    = x1v[b];
    const int X2    = x2v[b];
    const int xlo   = X1 & ~3;
    const int span4 = (((X2 + 3) & ~3) - xlo) >> 2;   // <= 128 float4s per row

    const size_t img_stride = (size_t)IMG_H * IMG_W;
    const float* base = img + (size_t)b * IMG_C * img_stride;

    // x taps loaded once, reused for all HGROUP rows
    const int2  xe = __ldg(&g_xtab[(b << 9) + tid]);
    const int   l0 = xe.x & 0xFFFF;
    const int   l1 = xe.x >> 16;
    const float wx = __int_as_float(xe.y);

    // ---- staging: HGROUP rows, loads independent across rows (high MLP) ----
    const int ns = IMG_C * span4;                     // <= 384 active threads
    const int c  = (tid >= span4) + (tid >= 2 * span4);
    const int xq = tid - c * span4;
#pragma unroll
    for (int r = 0; r < HGROUP; r++) {
        const int2  ye  = __ldg(&g_ytab[(b << 9) + hbase + r]);
        const int   ay0 = ye.x & 0xFFFF;
        const int   ay1 = ye.x >> 16;
        const float wy  = __int_as_float(ye.y);
        if (tid < ns) {
            const float* p = base + (size_t)c * img_stride + xlo + (xq << 2);
            const float4 v0 = *(const float4*)(p + (size_t)ay0 * IMG_W);
            const float4 v1 = *(const float4*)(p + (size_t)ay1 * IMG_W);
            float4 f;
            f.x = v0.x + (v1.x - v0.x) * wy;
            f.y = v0.y + (v1.y - v0.y) * wy;
            f.z = v0.z + (v1.z - v0.z) * wy;
            f.w = v0.w + (v1.w - v0.w) * wy;
            *(float4*)(&srow[(r * IMG_C + c) * SPITCH + (xq << 2)]) = f;
        }
    }
    __syncthreads();   // the ONLY barrier: amortized over 6144 outputs

    // ---- main: horizontal lerp, 2 LDS + 2 FFMA + 1 STG per output ----
    float* obase = out + (size_t)b * IMG_C * img_stride
                       + (size_t)hbase * IMG_W + tid;
#pragma unroll
    for (int r = 0; r < HGROUP; r++) {
#pragma unroll
        for (int cc = 0; cc < IMG_C; cc++) {
            const float f0 = srow[(r * IMG_C + cc) * SPITCH + l0];
            const float f1 = srow[(r * IMG_C + cc) * SPITCH + l1];
            obase[(size_t)cc * img_stride + (size_t)r * IMG_W] =
                f0 + (f1 - f0) * wx;
        }
    }
}

extern "C" void kernel_launch(void* const* d_in, const int* in_sizes, int n_in,
                              void* d_out, int out_size)
{
    const float* img = (const float*)d_in[0];
    const int*   y1  = (const int*)d_in[1];
    const int*   y2  = (const int*)d_in[2];
    const int*   x1  = (const int*)d_in[3];
    const int*   x2  = (const int*)d_in[4];
    float*       out = (float*)d_out;

    setup_tables_kernel<<<64, 512>>>(y1, y2, x1, x2);

    dim3 grid(IMG_H / HGROUP, 64);   // (row group, b)
    dim3 block(512);
    rand_crop_resize_kernel<<<grid, block>>>(img, x1, x2, out);
}

// round 7
// speedup vs baseline: 1.7961x; 1.2007x over previous
#include <cuda_runtime.h>
#include <cuda_bf16.h>
#include <cstddef>

// RandCropResize: tap tables + software-pipelined, double-buffered staging.
//
// Each block owns batch b and 16 consecutive output rows (8 groups x 2 rows).
// Pipeline per group g:
//   [STS: y-lerp prefetched regs -> sbuf[g&1]] -> [LDG prefetch group g+1
//   into regs] -> [__syncthreads] -> [main: horizontal lerp from sbuf[g&1]]
// The group-(g+1) loads have the whole group-g main phase (plus 3 other
// resident CTAs) to cover their latency; only the prologue load is exposed.
// One barrier per group is sufficient with double buffering (writes to
// buffer p at group g+2 are ordered after bar(g+1), which follows main(g)).

#define IMG_H 512
#define IMG_W 512
#define IMG_C 3
#define RPI   2               // rows per pipeline iteration
#define NITER 8               // iterations per block -> 16 rows/block
#define SPITCH 520            // smem row pitch (floats), float4-aligned

__device__ int2 g_xtab[64 * IMG_W];
__device__ int2 g_ytab[64 * IMG_H];

__global__ void __launch_bounds__(512)
setup_tables_kernel(const int* __restrict__ y1v, const int* __restrict__ y2v,
                    const int* __restrict__ x1v, const int* __restrict__ x2v)
{
    const int b = blockIdx.x;
    const int t = threadIdx.x;

    const int Y1 = y1v[b], Y2 = y2v[b];
    const int X1 = x1v[b], X2 = x2v[b];

    {   // y taps for h = t (absolute source rows)
        const int   ncy = Y2 - Y1;
        const float ny  = (float)ncy;
        float sy = ((float)t + 0.5f) * ny * (1.0f / (float)IMG_H) - 0.5f;
        sy = fminf(fmaxf(sy, 0.0f), ny - 1.0f);
        const int   iy0 = (int)floorf(sy);
        const int   iy1 = min(iy0 + 1, ncy - 1);
        const float wy  = sy - (float)iy0;
        int2 e;
        e.x = (Y1 + iy0) | ((Y1 + iy1) << 16);
        e.y = __float_as_int(wy);
        g_ytab[(b << 9) + t] = e;
    }
    {   // x taps for w = t (smem-relative: minus xlo)
        const int   xlo = X1 & ~3;
        const int   ncx = X2 - X1;
        const float nx  = (float)ncx;
        float sx = ((float)t + 0.5f) * nx * (1.0f / (float)IMG_W) - 0.5f;
        sx = fminf(fmaxf(sx, 0.0f), nx - 1.0f);
        const int   ix0 = (int)floorf(sx);
        const int   ix1 = min(ix0 + 1, ncx - 1);
        const float wx  = sx - (float)ix0;
        int2 e;
        e.x = ((X1 + ix0) - xlo) | (((X1 + ix1) - xlo) << 16);
        e.y = __float_as_int(wx);
        g_xtab[(b << 9) + t] = e;
    }
}

__global__ void __launch_bounds__(512, 4)
rand_crop_resize_kernel(const float* __restrict__ img,
                        const int* __restrict__ x1v,
                        const int* __restrict__ x2v,
                        float* __restrict__ out)
{
    __shared__ float sbuf[2][RPI * IMG_C * SPITCH];   // 2 x 12.2 KB

    const int hchunk = blockIdx.x * (RPI * NITER);    // 16 rows per block
    const int b      = blockIdx.y;
    const int tid    = threadIdx.x;

    const int X1    = x1v[b];
    const int X2    = x2v[b];
    const int xlo   = X1 & ~3;
    const int span4 = (((X2 + 3) & ~3) - xlo) >> 2;   // <= 128

    const size_t img_stride = (size_t)IMG_H * IMG_W;
    const float* base = img + (size_t)b * IMG_C * img_stride;

    // x taps: once per thread, reused for all 16 rows
    const int2  xe = __ldg(&g_xtab[(b << 9) + tid]);
    const int   l0 = xe.x & 0xFFFF;
    const int   l1 = xe.x >> 16;
    const float wx = __int_as_float(xe.y);

    // staging role (fixed per thread)
    const int  ns     = IMG_C * span4;                // <= 384
    const bool active = tid < ns;
    const int  c      = (tid >= span4) + (tid >= 2 * span4);
    const int  xq     = tid - c * span4;
    const float* pc   = base + (size_t)c * img_stride + xlo + (xq << 2);

    // prefetch registers for one group
    float4 pv0[RPI], pv1[RPI];
    float  pwy[RPI];

    // ---- prologue: load group 0 ----
#pragma unroll
    for (int r = 0; r < RPI; r++) {
        const int2 ye = __ldg(&g_ytab[(b << 9) + hchunk + r]);
        pwy[r] = __int_as_float(ye.y);
        if (active) {
            pv0[r] = *(const float4*)(pc + (size_t)(ye.x & 0xFFFF) * IMG_W);
            pv1[r] = *(const float4*)(pc + (size_t)(ye.x >> 16)   * IMG_W);
        }
    }

    float* const oblk = out + (size_t)b * IMG_C * img_stride
                            + (size_t)hchunk * IMG_W + tid;

    for (int g = 0; g < NITER; g++) {
        const int p = g & 1;

        // ---- STS: y-lerp the prefetched rows into smem ----
        if (active) {
#pragma unroll
            for (int r = 0; r < RPI; r++) {
                float4 f;
                f.x = pv0[r].x + (pv1[r].x - pv0[r].x) * pwy[r];
                f.y = pv0[r].y + (pv1[r].y - pv0[r].y) * pwy[r];
                f.z = pv0[r].z + (pv1[r].z - pv0[r].z) * pwy[r];
                f.w = pv0[r].w + (pv1[r].w - pv0[r].w) * pwy[r];
                *(float4*)(&sbuf[p][(r * IMG_C + c) * SPITCH + (xq << 2)]) = f;
            }
        }

        // ---- prefetch group g+1 (covered by this group's main phase) ----
        if (g + 1 < NITER) {
            const int hn = hchunk + (g + 1) * RPI;
#pragma unroll
            for (int r = 0; r < RPI; r++) {
                const int2 ye = __ldg(&g_ytab[(b << 9) + hn + r]);
                pwy[r] = __int_as_float(ye.y);
                if (active) {
                    pv0[r] = *(const float4*)(pc + (size_t)(ye.x & 0xFFFF) * IMG_W);
                    pv1[r] = *(const float4*)(pc + (size_t)(ye.x >> 16)   * IMG_W);
                }
            }
        }

        __syncthreads();   // one barrier per group

        // ---- main: horizontal lerp, 2 LDS + 2 FFMA + 1 STG per output ----
        float* og = oblk + (size_t)(g * RPI) * IMG_W;
#pragma unroll
        for (int r = 0; r < RPI; r++) {
#pragma unroll
            for (int cc = 0; cc < IMG_C; cc++) {
                const float f0 = sbuf[p][(r * IMG_C + cc) * SPITCH + l0];
                const float f1 = sbuf[p][(r * IMG_C + cc) * SPITCH + l1];
                og[(size_t)cc * img_stride + (size_t)r * IMG_W] =
                    f0 + (f1 - f0) * wx;
            }
        }
    }
}

extern "C" void kernel_launch(void* const* d_in, const int* in_sizes, int n_in,
                              void* d_out, int out_size)
{
    const float* img = (const float*)d_in[0];
    const int*   y1  = (const int*)d_in[1];
    const int*   y2  = (const int*)d_in[2];
    const int*   x1  = (const int*)d_in[3];
    const int*   x2  = (const int*)d_in[4];
    float*       out = (float*)d_out;

    setup_tables_kernel<<<64, 512>>>(y1, y2, x1, x2);

    dim3 grid(IMG_H / (RPI * NITER), 64);   // (row chunk, b) = (32, 64)
    dim3 block(512);
    rand_crop_resize_kernel<<<grid, block>>>(img, x1, x2, out);
}